// round 16
// baseline (speedup 1.0000x reference)
#include <cuda_runtime.h>
#include <cuda_bf16.h>
#include <math.h>
#include <stdint.h>

// Problem constants
#define Bn 32
#define Tn 512
#define Dn 768
#define Hn 256
#define Kc 32

// ---------------- scratch (device globals; no allocations allowed) ----------
__device__ float g_pre[16384 * 2048];      // [t*B+b][4H_f | 4H_b]  128 MB
__device__ float g_hcat[32 * 512 * 512];   // [b][t][h_f|h_b] 32 MB
__device__ float g_em[32 * 512 * 32];      // [b][t][k] 2 MB
__device__ float g_bloss[32];              // per-batch (num - logZ)
__device__ float g_hx2[2 * 2 * 4 * 2 * 1024]; // [parity][dir][grp][set][bb*256+u]
__device__ int   g_flag[8 * 2 * 8 * 32];   // [gi][set][slice] padded 128B

// bf16 two-way split operands for tensor-core GEMM
__device__ __nv_bfloat16 g_Ah[16384 * 768];
__device__ __nv_bfloat16 g_Al[16384 * 768];
__device__ __nv_bfloat16 g_Wh[2048 * 768];
__device__ __nv_bfloat16 g_Wl[2048 * 768];

// ---------------- helpers ----------------------------------------------------
__device__ __forceinline__ uint32_t s2u(const void* p) {
    uint32_t a;
    asm("{ .reg .u64 t; cvta.to.shared.u64 t, %1; cvt.u32.u64 %0, t; }" : "=r"(a) : "l"(p));
    return a;
}
__device__ __forceinline__ void cpa16(uint32_t dst, const void* src) {
    asm volatile("cp.async.cg.shared.global [%0], [%1], 16;" :: "r"(dst), "l"(src));
}
#define CP_COMMIT() asm volatile("cp.async.commit_group;")
#define CP_WAIT(n)  asm volatile("cp.async.wait_group %0;" :: "n"(n))

#define LDM4(r0, r1, r2, r3, addr) \
    asm volatile("ldmatrix.sync.aligned.m8n8.x4.shared.b16 {%0,%1,%2,%3}, [%4];" \
                 : "=r"(r0), "=r"(r1), "=r"(r2), "=r"(r3) : "r"(addr))

#define MMA16816(d, a, b) \
    asm volatile("mma.sync.aligned.m16n8k16.row.col.f32.bf16.bf16.f32 " \
                 "{%0,%1,%2,%3}, {%4,%5,%6,%7}, {%8,%9}, {%0,%1,%2,%3};" \
                 : "+f"((d)[0]), "+f"((d)[1]), "+f"((d)[2]), "+f"((d)[3]) \
                 : "r"((a)[0]), "r"((a)[1]), "r"((a)[2]), "r"((a)[3]), \
                   "r"((b)[0]), "r"((b)[1]))

// ---------------- init: zero flags (replay-safe) ----------------------------
__global__ void zero_flag_kernel() {
    int i = blockIdx.x * blockDim.x + threadIdx.x;
    if (i < 8 * 2 * 8 * 32) g_flag[i] = 0;
}

// ---------------- Phase A0: split fp32 -> 2x bf16 ---------------------------
__global__ void conv_x_kernel(const float* __restrict__ x) {
    int i4 = blockIdx.x * blockDim.x + threadIdx.x;
    if (i4 >= 16384 * 192) return;
    int i = i4 * 4;
    int r = i / 768, k = i - r * 768;
    int t = r >> 5, b = r & 31;
    float4 v = *(const float4*)(x + ((size_t)b * 512 + t) * 768 + k);
    float vv[4] = {v.x, v.y, v.z, v.w};
#pragma unroll
    for (int j = 0; j < 4; j++) {
        float val = vv[j];
        __nv_bfloat16 h = __float2bfloat16(val);
        g_Ah[i + j] = h;
        g_Al[i + j] = __float2bfloat16(val - __bfloat162float(h));
    }
}

__global__ void conv_w_kernel(const float* __restrict__ Wf, const float* __restrict__ Wb) {
    int i4 = blockIdx.x * blockDim.x + threadIdx.x;
    if (i4 >= 2048 * 192) return;
    int i = i4 * 4;
    int n = i / 768, k = i - n * 768;
    const float* src = (n < 1024) ? (Wf + (size_t)n * 768 + k)
                                  : (Wb + (size_t)(n - 1024) * 768 + k);
    float4 v = *(const float4*)src;
    float vv[4] = {v.x, v.y, v.z, v.w};
#pragma unroll
    for (int j = 0; j < 4; j++) {
        float val = vv[j];
        __nv_bfloat16 h = __float2bfloat16(val);
        g_Wh[i + j] = h;
        g_Wl[i + j] = __float2bfloat16(val - __bfloat162float(h));
    }
}

// ---------------- Phase A: pre = x @ [W_ih_f; W_ih_b]^T + bias --------------
#define STG_E 20480              // bf16 elems per stage (4 arrays * 128*40)
#define ARR_E 5120               // 128*40

__global__ __launch_bounds__(256, 1) void gemm_pre_mma(const float* __restrict__ bf_,
                                                       const float* __restrict__ bb_) {
    extern __shared__ __align__(16) __nv_bfloat16 smem[];
    __shared__ float bias_s[128];
    uint32_t sbase = s2u(smem);

    int tid = threadIdx.x;
    int lane = tid & 31, wid = tid >> 5;
    int wm = wid >> 2, wn = wid & 3;          // 2 x 4 warp grid
    int rowBase = blockIdx.y * 128, colBase = blockIdx.x * 128;

    if (tid < 128)
        bias_s[tid] = (colBase < 1024) ? bf_[colBase + tid] : bb_[colBase - 1024 + tid];

    int lr = tid >> 1, kh = (tid & 1) * 16;
    size_t arowg = (size_t)(rowBase + lr) * 768 + kh;
    size_t browg = (size_t)(colBase + lr) * 768 + kh;
    uint32_t drow = (uint32_t)(lr * 40 + kh) * 2;

    {
        uint32_t st = sbase;
        cpa16(st + 0 * ARR_E * 2 + drow,      g_Ah + arowg);
        cpa16(st + 0 * ARR_E * 2 + drow + 16, g_Ah + arowg + 8);
        cpa16(st + 1 * ARR_E * 2 + drow,      g_Al + arowg);
        cpa16(st + 1 * ARR_E * 2 + drow + 16, g_Al + arowg + 8);
        cpa16(st + 2 * ARR_E * 2 + drow,      g_Wh + browg);
        cpa16(st + 2 * ARR_E * 2 + drow + 16, g_Wh + browg + 8);
        cpa16(st + 3 * ARR_E * 2 + drow,      g_Wl + browg);
        cpa16(st + 3 * ARR_E * 2 + drow + 16, g_Wl + browg + 8);
        CP_COMMIT();
    }

    float acc[4][4][4];
#pragma unroll
    for (int i = 0; i < 4; i++)
#pragma unroll
        for (int j = 0; j < 4; j++)
#pragma unroll
            for (int q = 0; q < 4; q++) acc[i][j][q] = 0.f;

    int grp = lane >> 3, lrow = lane & 7;
    int rofs = lrow + (grp & 1) * 8;
    int cofs = (grp >> 1) * 8;

    for (int kt = 0; kt < 24; kt++) {
        if (kt < 23) {
            int k0 = (kt + 1) * 32;
            uint32_t st = sbase + ((kt + 1) & 1) * STG_E * 2;
            cpa16(st + 0 * ARR_E * 2 + drow,      g_Ah + arowg + k0);
            cpa16(st + 0 * ARR_E * 2 + drow + 16, g_Ah + arowg + k0 + 8);
            cpa16(st + 1 * ARR_E * 2 + drow,      g_Al + arowg + k0);
            cpa16(st + 1 * ARR_E * 2 + drow + 16, g_Al + arowg + k0 + 8);
            cpa16(st + 2 * ARR_E * 2 + drow,      g_Wh + browg + k0);
            cpa16(st + 2 * ARR_E * 2 + drow + 16, g_Wh + browg + k0 + 8);
            cpa16(st + 3 * ARR_E * 2 + drow,      g_Wl + browg + k0);
            cpa16(st + 3 * ARR_E * 2 + drow + 16, g_Wl + browg + k0 + 8);
            CP_COMMIT();
            CP_WAIT(1);
        } else {
            CP_WAIT(0);
        }
        __syncthreads();

        uint32_t st = sbase + (kt & 1) * STG_E * 2;
        uint32_t sAh = st, sAl = st + ARR_E * 2;
        uint32_t sBh = st + 2 * ARR_E * 2, sBl = st + 3 * ARR_E * 2;

#pragma unroll
        for (int kk = 0; kk < 32; kk += 16) {
            uint32_t bh[4][2], bl[4][2];
#pragma unroll
            for (int j2 = 0; j2 < 2; j2++) {
                int nrow = wn * 32 + j2 * 16 + rofs;
                uint32_t addr = sBh + (uint32_t)(nrow * 40 + kk + cofs) * 2;
                LDM4(bh[2 * j2][0], bh[2 * j2 + 1][0], bh[2 * j2][1], bh[2 * j2 + 1][1], addr);
                addr = sBl + (uint32_t)(nrow * 40 + kk + cofs) * 2;
                LDM4(bl[2 * j2][0], bl[2 * j2 + 1][0], bl[2 * j2][1], bl[2 * j2 + 1][1], addr);
            }
#pragma unroll
            for (int im = 0; im < 4; im++) {
                int mrow = wm * 64 + im * 16 + rofs;
                uint32_t a[4], al[4];
                uint32_t addr = sAh + (uint32_t)(mrow * 40 + kk + cofs) * 2;
                LDM4(a[0], a[1], a[2], a[3], addr);
                addr = sAl + (uint32_t)(mrow * 40 + kk + cofs) * 2;
                LDM4(al[0], al[1], al[2], al[3], addr);
#pragma unroll
                for (int in_ = 0; in_ < 4; in_++) {
                    MMA16816(acc[im][in_], a,  bh[in_]);
                    MMA16816(acc[im][in_], a,  bl[in_]);
                    MMA16816(acc[im][in_], al, bh[in_]);
                }
            }
        }
        __syncthreads();
    }

    int crow = lane >> 2, ccol = (lane & 3) * 2;
#pragma unroll
    for (int im = 0; im < 4; im++) {
        int r0 = rowBase + wm * 64 + im * 16 + crow;
#pragma unroll
        for (int in_ = 0; in_ < 4; in_++) {
            int c0loc = wn * 32 + in_ * 8 + ccol;
            int gc = colBase + c0loc;
            float2 v0, v1;
            v0.x = acc[im][in_][0] + bias_s[c0loc];
            v0.y = acc[im][in_][1] + bias_s[c0loc + 1];
            v1.x = acc[im][in_][2] + bias_s[c0loc];
            v1.y = acc[im][in_][3] + bias_s[c0loc + 1];
            *(float2*)(g_pre + (size_t)r0 * 2048 + gc) = v0;
            *(float2*)(g_pre + (size_t)(r0 + 8) * 2048 + gc) = v1;
        }
    }
}

// ---------------- Phase B: LSTM recurrence (2-set pipelined flag barrier) ---
// 64 blocks: dir(2) x grp(4, 8 batches) x slice(8, 32 units). Sets A/B of 4
// batches alternate so flag propagation hides behind the other set's compute.
__device__ __forceinline__ float sigf(float v) { return 1.f / (1.f + __expf(-v)); }

__device__ __forceinline__ void flag_release(int* f, int v) {
    asm volatile("st.release.gpu.global.b32 [%0], %1;" :: "l"(f), "r"(v) : "memory");
}
__device__ __forceinline__ void flag_poll(const int* f, int v) {
    int x;
    do {
        asm volatile("ld.acquire.gpu.global.b32 %0, [%1];" : "=r"(x) : "l"(f) : "memory");
    } while (x < v);
}

__global__ void __launch_bounds__(128, 1)
lstm_rec_kernel(const float* __restrict__ Whf,
                const float* __restrict__ Whb,
                const int* __restrict__ lengths) {
    extern __shared__ float sm[];
    float* h_sA = sm;                // [4 batches][260 (pad)]
    float* h_sB = sm + 4 * 260;      // [4 batches][260 (pad)]
    float* W_s  = sm + 8 * 260;      // [4 gates][32 units][260 (pad)]

    int tid = threadIdx.x;
    int bk = blockIdx.x;
    int dir = bk >> 5;
    int grp = (bk >> 3) & 3;
    int sl = bk & 7;
    int u0 = sl * 32;
    int u_loc = tid >> 2;
    int bb = tid & 3;
    int u = u0 + u_loc;
    int bA = grp * 8 + bb;
    int bB = grp * 8 + 4 + bb;
    int lenA = lengths[bA];
    int lenB = lengths[bB];
    const float* Wh = dir ? Whb : Whf;

    for (int idx = tid; idx < 4 * 32 * 256; idx += 128) {
        int g = idx >> 13;
        int rem = idx & 8191;
        int uu = rem >> 8;
        int k = rem & 255;
        W_s[(g * 32 + uu) * 260 + k] = Wh[((size_t)(g * 256 + u0 + uu)) * 256 + k];
    }
    for (int idx = tid; idx < 8 * 260; idx += 128) sm[idx] = 0.f;
    __syncthreads();

    int gi = dir * 4 + grp;
    int* flagA = g_flag + ((gi * 2 + 0) * 8 + sl) * 32;
    int* flagB = g_flag + ((gi * 2 + 1) * 8 + sl) * 32;
    int* fbA = g_flag + (gi * 2 + 0) * 8 * 32;
    int* fbB = g_flag + (gi * 2 + 1) * 8 * 32;
    // hx buffers: [parity][dir][grp][set][1024]
    float* hxA[2], *hxB[2];
#pragma unroll
    for (int p = 0; p < 2; p++) {
        hxA[p] = g_hx2 + (size_t)((((p * 2 + dir) * 4 + grp) * 2 + 0)) * 1024;
        hxB[p] = g_hx2 + (size_t)((((p * 2 + dir) * 4 + grp) * 2 + 1)) * 1024;
    }

    const float* wp0 = W_s + (0 * 32 + u_loc) * 260;
    const float* wp1 = W_s + (1 * 32 + u_loc) * 260;
    const float* wp2 = W_s + (2 * 32 + u_loc) * 260;
    const float* wp3 = W_s + (3 * 32 + u_loc) * 260;
    const float* hbA = h_sA + bb * 260;
    const float* hbB = h_sB + bb * 260;

    float cA = 0.f, cB = 0.f;

    // prefetch pre-activations for t = 0 (both sets)
    float nA0, nA1, nA2, nA3, nB0, nB1, nB2, nB3;
    {
        int ttA = (dir == 0) ? 0 : (lenA - 1);
        const float* pr = g_pre + ((size_t)ttA * 32 + bA) * 2048 + dir * 1024 + u;
        nA0 = pr[0]; nA1 = pr[256]; nA2 = pr[512]; nA3 = pr[768];
        int ttB = (dir == 0) ? 0 : (lenB - 1);
        const float* pq = g_pre + ((size_t)ttB * 32 + bB) * 2048 + dir * 1024 + u;
        nB0 = pq[0]; nB1 = pq[256]; nB2 = pq[512]; nB3 = pq[768];
    }

    // ---- prologue: A(0) (h = 0, so gates = pre) ----
    {
        float a0 = nA0, a1 = nA1, a2 = nA2, a3 = nA3;
        {   // prefetch A t=1
            int ttn = (dir == 0) ? 1 : ((1 < lenA) ? (lenA - 2) : 1);
            const float* prn = g_pre + ((size_t)ttn * 32 + bA) * 2048 + dir * 1024 + u;
            nA0 = prn[0]; nA1 = prn[256]; nA2 = prn[512]; nA3 = prn[768];
        }
        cA = sigf(a0) * tanhf(a2);
        float hn = sigf(a3) * tanhf(cA);
        int ttA = (dir == 0) ? 0 : (lenA - 1);
        g_hcat[((size_t)bA * 512 + ttA) * 512 + dir * 256 + u] = hn;
        __stcg(&hxA[0][bb * 256 + u], hn);
        __syncthreads();
        if (tid == 0) flag_release(flagA, 1);
    }

    for (int t = 0; t < 512; t++) {
        int p = t & 1;
        // ---- compute B(t) ----
        {
            float a0 = nB0, a1 = nB1, a2 = nB2, a3 = nB3;
            {
                int tn = (t + 1 < 512) ? (t + 1) : 511;
                int ttn = (dir == 0) ? tn : ((tn < lenB) ? (lenB - 1 - tn) : tn);
                const float* prn = g_pre + ((size_t)ttn * 32 + bB) * 2048 + dir * 1024 + u;
                nB0 = prn[0]; nB1 = prn[256]; nB2 = prn[512]; nB3 = prn[768];
            }
#pragma unroll 8
            for (int k4 = 0; k4 < 64; k4++) {
                float4 hv = ((const float4*)hbB)[k4];
                float4 w0 = ((const float4*)wp0)[k4];
                float4 w1 = ((const float4*)wp1)[k4];
                float4 w2 = ((const float4*)wp2)[k4];
                float4 w3 = ((const float4*)wp3)[k4];
                a0 += hv.x * w0.x + hv.y * w0.y + hv.z * w0.z + hv.w * w0.w;
                a1 += hv.x * w1.x + hv.y * w1.y + hv.z * w1.z + hv.w * w1.w;
                a2 += hv.x * w2.x + hv.y * w2.y + hv.z * w2.z + hv.w * w2.w;
                a3 += hv.x * w3.x + hv.y * w3.y + hv.z * w3.z + hv.w * w3.w;
            }
            cB = sigf(a1) * cB + sigf(a0) * tanhf(a2);
            float hn = sigf(a3) * tanhf(cB);
            int ttB = (dir == 0) ? t : ((t < lenB) ? (lenB - 1 - t) : t);
            g_hcat[((size_t)bB * 512 + ttB) * 512 + dir * 256 + u] = hn;
            __stcg(&hxB[p][bb * 256 + u], hn);
            __syncthreads();
            if (tid == 0) flag_release(flagB, t + 1);
        }
        // ---- poll + gather A(t) (published ~1 compute ago) ----
        if (tid < 8) flag_poll(fbA + tid * 32, t + 1);
        __syncthreads();
#pragma unroll
        for (int i = 0; i < 8; i++) {
            int j = tid + i * 128;
            h_sA[(j >> 8) * 260 + (j & 255)] = __ldcg(&hxA[p][j]);
        }
        __syncthreads();
        if (t < 511) {
            // ---- compute A(t+1) ----
            float a0 = nA0, a1 = nA1, a2 = nA2, a3 = nA3;
            {
                int tn = (t + 2 < 512) ? (t + 2) : 511;
                int ttn = (dir == 0) ? tn : ((tn < lenA) ? (lenA - 1 - tn) : tn);
                const float* prn = g_pre + ((size_t)ttn * 32 + bA) * 2048 + dir * 1024 + u;
                nA0 = prn[0]; nA1 = prn[256]; nA2 = prn[512]; nA3 = prn[768];
            }
#pragma unroll 8
            for (int k4 = 0; k4 < 64; k4++) {
                float4 hv = ((const float4*)hbA)[k4];
                float4 w0 = ((const float4*)wp0)[k4];
                float4 w1 = ((const float4*)wp1)[k4];
                float4 w2 = ((const float4*)wp2)[k4];
                float4 w3 = ((const float4*)wp3)[k4];
                a0 += hv.x * w0.x + hv.y * w0.y + hv.z * w0.z + hv.w * w0.w;
                a1 += hv.x * w1.x + hv.y * w1.y + hv.z * w1.z + hv.w * w1.w;
                a2 += hv.x * w2.x + hv.y * w2.y + hv.z * w2.z + hv.w * w2.w;
                a3 += hv.x * w3.x + hv.y * w3.y + hv.z * w3.z + hv.w * w3.w;
            }
            cA = sigf(a1) * cA + sigf(a0) * tanhf(a2);
            float hn = sigf(a3) * tanhf(cA);
            int ts = t + 1;
            int ttA = (dir == 0) ? ts : ((ts < lenA) ? (lenA - 1 - ts) : ts);
            g_hcat[((size_t)bA * 512 + ttA) * 512 + dir * 256 + u] = hn;
            __stcg(&hxA[ts & 1][bb * 256 + u], hn);
            __syncthreads();
            if (tid == 0) flag_release(flagA, t + 2);

            // ---- poll + gather B(t) ----
            if (tid < 8) flag_poll(fbB + tid * 32, t + 1);
            __syncthreads();
#pragma unroll
            for (int i = 0; i < 8; i++) {
                int j = tid + i * 128;
                h_sB[(j >> 8) * 260 + (j & 255)] = __ldcg(&hxB[p][j]);
            }
            __syncthreads();
        }
    }
}

// ---------------- Phase C: emissions = hcat @ W_clf^T + b_clf ---------------
__global__ void emis_kernel(const float* __restrict__ Wclf,
                            const float* __restrict__ bclf) {
    extern __shared__ float smc[];
    float* Wt = smc;              // [512][32] transposed W_clf
    float* hrow = smc + 512 * 32; // [8 warps][512]
    int tid = threadIdx.x;
    for (int idx = tid; idx < 32 * 512; idx += 256) {
        int k = idx >> 9, j = idx & 511;
        Wt[j * 32 + k] = Wclf[idx];
    }
    __syncthreads();
    int w = tid >> 5, lane = tid & 31;
    float bk = bclf[lane];
    float* hs = hrow + w * 512;
    int rend = blockIdx.x * 128 + 128;
    for (int r = blockIdx.x * 128 + w; r < rend; r += 8) {
        const float4* src = (const float4*)(g_hcat + (size_t)r * 512);
#pragma unroll
        for (int i = 0; i < 4; i++) ((float4*)hs)[lane + i * 32] = src[lane + i * 32];
        __syncwarp();
        float acc = bk;
#pragma unroll 8
        for (int j4 = 0; j4 < 128; j4++) {
            float4 h4 = ((const float4*)hs)[j4];
            acc += h4.x * Wt[(j4 * 4 + 0) * 32 + lane] + h4.y * Wt[(j4 * 4 + 1) * 32 + lane]
                 + h4.z * Wt[(j4 * 4 + 2) * 32 + lane] + h4.w * Wt[(j4 * 4 + 3) * 32 + lane];
        }
        g_em[(size_t)r * 32 + lane] = acc;
        __syncwarp();
    }
}

// ---------------- Phase D: CRF NLL (per-batch warp) -------------------------
__global__ void crf_nll_kernel(const int* __restrict__ lengths,
                               const int* __restrict__ targets,
                               const float* __restrict__ start_t,
                               const float* __restrict__ end_t,
                               const float* __restrict__ trans) {
    __shared__ float tr[32 * 33];
    int b = blockIdx.x, lane = threadIdx.x;
    for (int idx = lane; idx < 1024; idx += 32) tr[(idx >> 5) * 33 + (idx & 31)] = trans[idx];
    __syncwarp();
    int len = lengths[b];
    const int* tg = targets + b * 512;

    float part = 0.f;
    for (int t = 1 + lane; t < 512; t += 32)
        if (t < len)
            part += trans[tg[t - 1] * 32 + tg[t]] + g_em[((size_t)b * 512 + t) * 32 + tg[t]];
    for (int off = 16; off; off >>= 1) part += __shfl_down_sync(0xffffffffu, part, off);
    float num = 0.f;
    if (lane == 0)
        num = part + start_t[tg[0]] + g_em[((size_t)b * 512) * 32 + tg[0]] + end_t[tg[len - 1]];

    float alpha = start_t[lane] + g_em[((size_t)b * 512) * 32 + lane];
    for (int t = 1; t < 512; t++) {
        float e = g_em[((size_t)b * 512 + t) * 32 + lane];
        float m = -3.402823e38f;
#pragma unroll
        for (int i = 0; i < 32; i++) {
            float v = __shfl_sync(0xffffffffu, alpha, i) + tr[i * 33 + lane];
            m = fmaxf(m, v);
        }
        float s = 0.f;
#pragma unroll
        for (int i = 0; i < 32; i++) {
            float v = __shfl_sync(0xffffffffu, alpha, i) + tr[i * 33 + lane];
            s += __expf(v - m);
        }
        float nxt = m + __logf(s) + e;
        alpha = (t < len) ? nxt : alpha;
    }
    float v = alpha + end_t[lane];
    float mm = v;
    for (int off = 16; off; off >>= 1) mm = fmaxf(mm, __shfl_xor_sync(0xffffffffu, mm, off));
    float se = __expf(v - mm);
    for (int off = 16; off; off >>= 1) se += __shfl_xor_sync(0xffffffffu, se, off);
    if (lane == 0) g_bloss[b] = num - (mm + __logf(se));
}

__global__ void finalize_loss_kernel(float* out) {
    int lane = threadIdx.x;
    float v = g_bloss[lane];
    for (int off = 16; off; off >>= 1) v += __shfl_down_sync(0xffffffffu, v, off);
    if (lane == 0) out[0] = -v * (1.f / 32.f);
}

// ---------------- Phase E: Viterbi decode (per-batch warp) ------------------
__global__ void viterbi_kernel(const int* __restrict__ lengths,
                               const float* __restrict__ start_t,
                               const float* __restrict__ end_t,
                               const float* __restrict__ trans,
                               float* __restrict__ out) {
    __shared__ float tr[32 * 33];
    __shared__ unsigned char hist[511 * 32];
    int b = blockIdx.x, lane = threadIdx.x;
    for (int idx = lane; idx < 1024; idx += 32) tr[(idx >> 5) * 33 + (idx & 31)] = trans[idx];
    __syncwarp();
    int len = lengths[b];

    float score = start_t[lane] + g_em[((size_t)b * 512) * 32 + lane];
    for (int t = 1; t < 512; t++) {
        float e = g_em[((size_t)b * 512 + t) * 32 + lane];
        float m = -3.402823e38f;
        int arg = 0;
#pragma unroll
        for (int i = 0; i < 32; i++) {
            float v = __shfl_sync(0xffffffffu, score, i) + tr[i * 33 + lane];
            if (v > m) { m = v; arg = i; }
        }
        bool valid = (t < len);
        hist[(t - 1) * 32 + lane] = (unsigned char)(valid ? arg : lane);
        score = valid ? (m + e) : score;
    }
    float bv = score + end_t[lane];
    int bi = lane;
    for (int off = 16; off; off >>= 1) {
        float ov = __shfl_down_sync(0xffffffffu, bv, off);
        int oi = __shfl_down_sync(0xffffffffu, bi, off);
        if (ov > bv || (ov == bv && oi < bi)) { bv = ov; bi = oi; }
    }
    int last = __shfl_sync(0xffffffffu, bi, 0);
    if (lane == 0) {
        int tag = last;
        out[1 + b * 512 + 511] = (511 < len) ? (float)tag : 0.f;
        for (int s = 510; s >= 0; s--) {
            tag = hist[s * 32 + tag];
            out[1 + b * 512 + s] = (s < len) ? (float)tag : 0.f;
        }
    }
}

// ---------------- launch ----------------------------------------------------
extern "C" void kernel_launch(void* const* d_in, const int* in_sizes, int n_in,
                              void* d_out, int out_size) {
    const float* x       = (const float*)d_in[0];
    const int*   lengths = (const int*)  d_in[1];
    const int*   targets = (const int*)  d_in[3];
    const float* W_ih_f  = (const float*)d_in[4];
    const float* W_hh_f  = (const float*)d_in[5];
    const float* b_f     = (const float*)d_in[6];
    const float* W_ih_b  = (const float*)d_in[7];
    const float* W_hh_b  = (const float*)d_in[8];
    const float* b_b     = (const float*)d_in[9];
    const float* W_clf   = (const float*)d_in[10];
    const float* b_clf   = (const float*)d_in[11];
    const float* start_t = (const float*)d_in[12];
    const float* end_t   = (const float*)d_in[13];
    const float* trans   = (const float*)d_in[14];
    float* out = (float*)d_out;

    zero_flag_kernel<<<16, 256>>>();

    conv_x_kernel<<<(16384 * 192 + 255) / 256, 256>>>(x);
    conv_w_kernel<<<(2048 * 192 + 255) / 256, 256>>>(W_ih_f, W_ih_b);

    int smem_g = 2 * STG_E * 2;  // 81920 B
    cudaFuncSetAttribute(gemm_pre_mma, cudaFuncAttributeMaxDynamicSharedMemorySize, smem_g);
    dim3 gg(16, 128);
    gemm_pre_mma<<<gg, 256, smem_g>>>(b_f, b_b);

    int smem_rec = (8 * 260 + 4 * 32 * 260) * 4;  // 141440 B
    cudaFuncSetAttribute(lstm_rec_kernel, cudaFuncAttributeMaxDynamicSharedMemorySize, smem_rec);
    lstm_rec_kernel<<<64, 128, smem_rec>>>(W_hh_f, W_hh_b, lengths);

    int smem_em = (512 * 32 + 8 * 512) * 4;
    cudaFuncSetAttribute(emis_kernel, cudaFuncAttributeMaxDynamicSharedMemorySize, smem_em);
    emis_kernel<<<128, 256, smem_em>>>(W_clf, b_clf);

    crf_nll_kernel<<<32, 32>>>(lengths, targets, start_t, end_t, trans);
    finalize_loss_kernel<<<1, 32>>>(out);
    viterbi_kernel<<<32, 32>>>(lengths, start_t, end_t, trans, out);
}